// round 10
// baseline (speedup 1.0000x reference)
#include <cuda_runtime.h>
#include <cuda_bf16.h>
#include <stdint.h>

#define Bb 16
#define Qd 2048
#define Kd 2048
#define Fd 128
#define KT 64
#define NT 256

// smem word offsets (uint32 words)
#define W_QS   0                       // [128][68]
#define W_KS   8704                    // 2 x [64][68]
#define W_VI   17408                   // 2 x [32 kw][264]
#define W_MBA  34304                   // 2 x [128][2] packed am bits
#define W_MBL  34816                   // 2 x [128][2] packed alm bits
#define W_CKS  35328                   // 2 x [128] floats (ck coords)
#define SMEM_WORDS 35584
#define SMEM_BYTES (SMEM_WORDS*4)
#define SMEM1_BYTES ((8704 + 2*4352)*4)

#define KSTRIDE 4352
#define VSTRIDE 8448

#define PACKBF2(r, lo, hi) asm("cvt.rn.bf16x2.f32 %0, %1, %2;" : "=r"(r) : "f"(hi), "f"(lo))
#define EX2(d, x) asm("ex2.approx.f32 %0, %1;" : "=f"(d) : "f"(x))
#define SQRTA(d, x) asm("sqrt.approx.f32 %0, %1;" : "=f"(d) : "f"(x))

__device__ float g_lsum[Bb * Qd];

__device__ __forceinline__ void mma16816(float& c0, float& c1, float& c2, float& c3,
                                         uint32_t a0, uint32_t a1, uint32_t a2, uint32_t a3,
                                         uint32_t b0, uint32_t b1) {
    asm volatile("mma.sync.aligned.m16n8k16.row.col.f32.bf16.bf16.f32 "
        "{%0,%1,%2,%3}, {%4,%5,%6,%7}, {%8,%9}, {%0,%1,%2,%3};"
        : "+f"(c0), "+f"(c1), "+f"(c2), "+f"(c3)
        : "r"(a0), "r"(a1), "r"(a2), "r"(a3), "r"(b0), "r"(b1));
}

#define LDSM4(d0, d1, d2, d3, addr) \
    asm volatile("ldmatrix.sync.aligned.m8n8.x4.shared.b16 {%0,%1,%2,%3}, [%4];" \
        : "=r"(d0), "=r"(d1), "=r"(d2), "=r"(d3) : "r"(addr))

extern __shared__ uint32_t smw[];

// ---------------- kernel 1: softmax denominators (double-buffered K) ----------------
__global__ void __launch_bounds__(NT, 1) lsum_kernel(
    const float* __restrict__ q, const float* __restrict__ k)
{
    const int b = blockIdx.y, q0 = blockIdx.x * 128;
    const int tid = threadIdx.x;
    const int wid = tid >> 5, lane = tid & 31;
    const int gid = lane >> 2, tig = lane & 3;

    uint32_t* QS = smw;
    uint32_t* KS = smw + 8704;

    const float C1 = 0.12753859788f;   // log2(e)/sqrt(128)
    const float C0 = -23.0831206f;     // -16*log2(e)

    {
        const float* qp = q + ((size_t)b * Qd + q0) * Fd;
        #pragma unroll
        for (int it = 0; it < 16; it++) {
            int widx = tid + it * 256;          // 4096 float4 = 128 rows x 32
            int row = widx >> 5, w4 = widx & 31;
            float4 t = *(const float4*)(qp + row * Fd + 4 * w4);
            uint32_t p0, p1;
            PACKBF2(p0, t.x, t.y);
            PACKBF2(p1, t.z, t.w);
            *(uint2*)(QS + row * 68 + 2 * w4) = make_uint2(p0, p1);
        }
    }

    const float* kbase = k + (size_t)b * Kd * Fd;
    auto load_k = [&](int t, int bf) {
        const float* kp = kbase + (size_t)t * KT * Fd;
        uint32_t* KSb = KS + bf * KSTRIDE;
        #pragma unroll
        for (int it = 0; it < 8; it++) {
            int widx = tid + it * 256;          // 2048 float4 = 64 rows x 32
            int row = widx >> 5, w4 = widx & 31;
            float4 tt = *(const float4*)(kp + row * Fd + 4 * w4);
            uint32_t p0, p1;
            PACKBF2(p0, tt.x, tt.y);
            PACKBF2(p1, tt.z, tt.w);
            *(uint2*)(KSb + row * 68 + 2 * w4) = make_uint2(p0, p1);
        }
    };

    const int lm = lane >> 3, lr = lane & 7;
    const uint32_t qsb = (uint32_t)__cvta_generic_to_shared(QS);
    const uint32_t ksb = (uint32_t)__cvta_generic_to_shared(KS);
    const uint32_t aAddr0 = qsb + (((wid * 16 + ((lm & 1) << 3) + lr) * 68) + ((lm >> 1) << 2)) * 4;
    const uint32_t bAddr0 = ksb + (((((lm >> 1) << 3) + lr) * 68) + ((lm & 1) << 2)) * 4;

    float lsum0 = 0.f, lsum1 = 0.f;

    load_k(0, 0);
    __syncthreads();

    for (int t = 0; t < 32; t++) {
        const int bf = t & 1;
        if (t < 31) load_k(t + 1, bf ^ 1);

        const uint32_t bA = bAddr0 + bf * (KSTRIDE * 4);

        float sc[8][4];
        #pragma unroll
        for (int j = 0; j < 8; j++)
            #pragma unroll
            for (int c = 0; c < 4; c++) sc[j][c] = 0.f;

        #pragma unroll
        for (int ks = 0; ks < 8; ks++) {
            uint32_t a0, a1, a2, a3;
            LDSM4(a0, a1, a2, a3, aAddr0 + ks * 32);
            #pragma unroll
            for (int jp = 0; jp < 4; jp++) {
                uint32_t b0, b1, b2, b3;
                LDSM4(b0, b1, b2, b3, bA + jp * (16 * 68 * 4) + ks * 32);
                mma16816(sc[2*jp][0], sc[2*jp][1], sc[2*jp][2], sc[2*jp][3],
                         a0, a1, a2, a3, b0, b1);
                mma16816(sc[2*jp+1][0], sc[2*jp+1][1], sc[2*jp+1][2], sc[2*jp+1][3],
                         a0, a1, a2, a3, b2, b3);
            }
        }
        #pragma unroll
        for (int j = 0; j < 8; j++) {
            float e0, e1, e2, e3;
            EX2(e0, fmaf(sc[j][0], C1, C0));
            EX2(e1, fmaf(sc[j][1], C1, C0));
            EX2(e2, fmaf(sc[j][2], C1, C0));
            EX2(e3, fmaf(sc[j][3], C1, C0));
            lsum0 += e0 + e1;
            lsum1 += e2 + e3;
        }
        __syncthreads();
    }

    lsum0 += __shfl_xor_sync(0xffffffffu, lsum0, 1);
    lsum0 += __shfl_xor_sync(0xffffffffu, lsum0, 2);
    lsum1 += __shfl_xor_sync(0xffffffffu, lsum1, 1);
    lsum1 += __shfl_xor_sync(0xffffffffu, lsum1, 2);
    if (tig == 0) {
        g_lsum[(size_t)b * Qd + q0 + wid * 16 + gid] = lsum0;
        g_lsum[(size_t)b * Qd + q0 + wid * 16 + gid + 8] = lsum1;
    }
}

// ---------------- kernel 2: P = softmax - dist, O = P @ V ----------------
__global__ void __launch_bounds__(NT, 1) alibi_main_kernel(
    const float* __restrict__ q, const float* __restrict__ k, const float* __restrict__ v,
    const float* __restrict__ cq, const float* __restrict__ ck,
    const int* __restrict__ am, const int* __restrict__ alm,
    const float* __restrict__ bias_scale, const float* __restrict__ running_mean,
    float* __restrict__ out)
{
    const int b = blockIdx.y, q0 = blockIdx.x * 128;
    const int tid = threadIdx.x;
    const int wid = tid >> 5, lane = tid & 31;
    const int gid = lane >> 2, tig = lane & 3;

    uint32_t* QS  = smw + W_QS;
    uint32_t* KS  = smw + W_KS;
    uint32_t* VI  = smw + W_VI;
    uint32_t* MBA = smw + W_MBA;
    uint32_t* MBL = smw + W_MBL;
    float*    CKS = (float*)(smw + W_CKS);

    const float dscale = bias_scale[0] / running_mean[0];
    const float C1 = 0.12753859788f;
    const float C0 = -23.0831206f;

    {
        const float* qp = q + ((size_t)b * Qd + q0) * Fd;
        #pragma unroll
        for (int it = 0; it < 16; it++) {
            int widx = tid + it * 256;
            int row = widx >> 5, w4 = widx & 31;
            float4 t = *(const float4*)(qp + row * Fd + 4 * w4);
            uint32_t p0, p1;
            PACKBF2(p0, t.x, t.y);
            PACKBF2(p1, t.z, t.w);
            *(uint2*)(QS + row * 68 + 2 * w4) = make_uint2(p0, p1);
        }
    }

    const int r0l = wid * 16 + gid;
    const size_t r0g = (size_t)b * Qd + q0 + r0l;
    const size_t r1g = r0g + 8;
    const float cqx0 = cq[2 * r0g], cqy0 = cq[2 * r0g + 1];
    const float cqx1 = cq[2 * r1g], cqy1 = cq[2 * r1g + 1];
    const float inv0 = 1.f / g_lsum[r0g];
    const float inv1 = 1.f / g_lsum[r1g];

    // tile loader (K, V, masks->bits, ck)
    const int mrow = tid >> 1, mhalf = tid & 1;
    const int* amp_base = am  + ((size_t)b * Qd + q0 + mrow) * Kd + mhalf * 32;
    const int* alp_base = alm + ((size_t)b * Qd + q0 + mrow) * Kd + mhalf * 32;
    auto load_tile = [&](int t, int bf) {
        const int k0 = t * KT;
        uint32_t* KSb = KS + bf * KSTRIDE;
        uint32_t* VIb = VI + bf * VSTRIDE;
        const float* kp = k + ((size_t)b * Kd + k0) * Fd;
        #pragma unroll
        for (int it = 0; it < 8; it++) {
            int widx = tid + it * 256;
            int row = widx >> 5, w4 = widx & 31;
            float4 tt = *(const float4*)(kp + row * Fd + 4 * w4);
            uint32_t p0, p1;
            PACKBF2(p0, tt.x, tt.y);
            PACKBF2(p1, tt.z, tt.w);
            *(uint2*)(KSb + row * 68 + 2 * w4) = make_uint2(p0, p1);
        }
        const float* vp = v + ((size_t)b * Kd + k0) * Fd;
        #pragma unroll
        for (int it = 0; it < 4; it++) {
            int idx = tid + it * 256;            // 1024 = 32 kw x 32 fq
            int fq = idx & 31, kw = idx >> 5;
            const float* va = vp + (size_t)(2 * kw) * Fd + 4 * fq;
            float4 a = *(const float4*)va;
            float4 bb = *(const float4*)(va + Fd);
            uint32_t ph0, ph1, ph2, ph3;
            PACKBF2(ph0, a.x, bb.x);
            PACKBF2(ph1, a.y, bb.y);
            PACKBF2(ph2, a.z, bb.z);
            PACKBF2(ph3, a.w, bb.w);
            uint32_t pl0, pl1, pl2, pl3;
            float r0, r1;
            r0 = a.x - __uint_as_float(ph0 << 16); r1 = bb.x - __uint_as_float(ph0 & 0xffff0000u);
            PACKBF2(pl0, r0, r1);
            r0 = a.y - __uint_as_float(ph1 << 16); r1 = bb.y - __uint_as_float(ph1 & 0xffff0000u);
            PACKBF2(pl1, r0, r1);
            r0 = a.z - __uint_as_float(ph2 << 16); r1 = bb.z - __uint_as_float(ph2 & 0xffff0000u);
            PACKBF2(pl2, r0, r1);
            r0 = a.w - __uint_as_float(ph3 << 16); r1 = bb.w - __uint_as_float(ph3 & 0xffff0000u);
            PACKBF2(pl3, r0, r1);
            int base = kw * 264 + 8 * fq;
            *(uint4*)(VIb + base)     = make_uint4(ph0, pl0, ph1, pl1);
            *(uint4*)(VIb + base + 4) = make_uint4(ph2, pl2, ph3, pl3);
        }
        // masks -> packed bits
        {
            const int4* amp = (const int4*)(amp_base + k0);
            const int4* alp = (const int4*)(alp_base + k0);
            uint32_t wa = 0, wl = 0;
            #pragma unroll
            for (int i = 0; i < 8; i++) {
                int4 ma = amp[i];
                wa |= (uint32_t)(ma.x | (ma.y << 1) | (ma.z << 2) | (ma.w << 3)) << (4 * i);
                int4 ml = alp[i];
                wl |= (uint32_t)(ml.x | (ml.y << 1) | (ml.z << 2) | (ml.w << 3)) << (4 * i);
            }
            MBA[bf * 256 + mrow * 2 + mhalf] = wa;
            MBL[bf * 256 + mrow * 2 + mhalf] = wl;
        }
        if (tid < 128)
            CKS[bf * 128 + tid] = ck[((size_t)b * Kd + k0) * 2 + tid];
    };

    // ldmatrix lane addressing
    const int lm = lane >> 3, lr = lane & 7;
    const uint32_t qsb = (uint32_t)__cvta_generic_to_shared(QS);
    const uint32_t ksb = (uint32_t)__cvta_generic_to_shared(KS);
    const uint32_t aAddr0 = qsb + (((wid * 16 + ((lm & 1) << 3) + lr) * 68) + ((lm >> 1) << 2)) * 4;
    const uint32_t bAddr0 = ksb + (((((lm >> 1) << 3) + lr) * 68) + ((lm & 1) << 2)) * 4;

    float acc[16][4];
    #pragma unroll
    for (int jn = 0; jn < 16; jn++)
        #pragma unroll
        for (int c = 0; c < 4; c++) acc[jn][c] = 0.f;

    load_tile(0, 0);
    __syncthreads();

    for (int t = 0; t < 32; t++) {
        const int bf = t & 1;
        if (t < 31) load_tile(t + 1, bf ^ 1);

        // ---- S = Q @ K^T ----
        const uint32_t bA = bAddr0 + bf * (KSTRIDE * 4);
        float sc[8][4];
        #pragma unroll
        for (int j = 0; j < 8; j++)
            #pragma unroll
            for (int c = 0; c < 4; c++) sc[j][c] = 0.f;

        #pragma unroll
        for (int ks = 0; ks < 8; ks++) {
            uint32_t a0, a1, a2, a3;
            LDSM4(a0, a1, a2, a3, aAddr0 + ks * 32);
            #pragma unroll
            for (int jp = 0; jp < 4; jp++) {
                uint32_t b0, b1, b2, b3;
                LDSM4(b0, b1, b2, b3, bA + jp * (16 * 68 * 4) + ks * 32);
                mma16816(sc[2*jp][0], sc[2*jp][1], sc[2*jp][2], sc[2*jp][3],
                         a0, a1, a2, a3, b0, b1);
                mma16816(sc[2*jp+1][0], sc[2*jp+1][1], sc[2*jp+1][2], sc[2*jp+1][3],
                         a0, a1, a2, a3, b2, b3);
            }
        }

        // mask words for this thread's two rows
        const uint32_t* MBAb = MBA + bf * 256;
        const uint32_t* MBLb = MBL + bf * 256;
        uint2 a0w = *(const uint2*)(MBAb + r0l * 2);
        uint2 a1w = *(const uint2*)(MBAb + (r0l + 8) * 2);
        uint2 l0w = *(const uint2*)(MBLb + r0l * 2);
        uint2 l1w = *(const uint2*)(MBLb + (r0l + 8) * 2);
        uint2 o0w = make_uint2(a0w.x | l0w.x, a0w.y | l0w.y);
        uint2 o1w = make_uint2(a1w.x | l1w.x, a1w.y | l1w.y);
        const float* CKSb = CKS + bf * 128;
        uint32_t* VIb = VI + bf * VSTRIDE;

        // ---- per k16-chunk: elementwise P, then PV ----
        #pragma unroll
        for (int ks = 0; ks < 4; ks++) {
            uint32_t HA0, HA1, HB0, HB1, LA0, LA1, LB0, LB1;
            #pragma unroll
            for (int jj = 0; jj < 2; jj++) {
                const int j = 2 * ks + jj;
                const int sh = (j & 3) * 8 + tig * 2;
                const uint32_t wa0 = (j < 4) ? a0w.x : a0w.y;
                const uint32_t wa1 = (j < 4) ? a1w.x : a1w.y;
                const uint32_t wo0 = (j < 4) ? o0w.x : o0w.y;
                const uint32_t wo1 = (j < 4) ? o1w.x : o1w.y;

                float4 ckv = *(const float4*)(CKSb + j * 16 + tig * 4);

                float e00, e01, e10, e11;
                EX2(e00, fmaf(sc[j][0], C1, C0));
                EX2(e01, fmaf(sc[j][1], C1, C0));
                EX2(e10, fmaf(sc[j][2], C1, C0));
                EX2(e11, fmaf(sc[j][3], C1, C0));

                float dxa = cqx0 - ckv.x, dya = cqy0 - ckv.y;
                float dxb = cqx0 - ckv.z, dyb = cqy0 - ckv.w;
                float dxc = cqx1 - ckv.x, dyc = cqy1 - ckv.y;
                float dxd = cqx1 - ckv.z, dyd = cqy1 - ckv.w;
                float d00, d01, d10, d11;
                SQRTA(d00, fmaf(dxa, dxa, dya * dya));
                SQRTA(d01, fmaf(dxb, dxb, dyb * dyb));
                SQRTA(d10, fmaf(dxc, dxc, dyc * dyc));
                SQRTA(d11, fmaf(dxd, dxd, dyd * dyd));

                d00 = ((wo0 >> sh) & 1)       ? 0.f : d00 * dscale;
                d01 = ((wo0 >> (sh + 1)) & 1) ? 0.f : d01 * dscale;
                d10 = ((wo1 >> sh) & 1)       ? 0.f : d10 * dscale;
                d11 = ((wo1 >> (sh + 1)) & 1) ? 0.f : d11 * dscale;

                float p00 = (((wa0 >> sh) & 1)       ? 0.f : e00 * inv0) - d00;
                float p01 = (((wa0 >> (sh + 1)) & 1) ? 0.f : e01 * inv0) - d01;
                float p10 = (((wa1 >> sh) & 1)       ? 0.f : e10 * inv1) - d10;
                float p11 = (((wa1 >> (sh + 1)) & 1) ? 0.f : e11 * inv1) - d11;

                uint32_t h0, h1, l0, l1;
                PACKBF2(h0, p00, p01);
                PACKBF2(h1, p10, p11);
                float q00 = p00 - __uint_as_float(h0 << 16);
                float q01 = p01 - __uint_as_float(h0 & 0xffff0000u);
                float q10 = p10 - __uint_as_float(h1 << 16);
                float q11 = p11 - __uint_as_float(h1 & 0xffff0000u);
                PACKBF2(l0, q00, q01);
                PACKBF2(l1, q10, q11);
                if (jj == 0) { HA0 = h0; HA1 = h1; LA0 = l0; LA1 = l1; }
                else         { HB0 = h0; HB1 = h1; LB0 = l0; LB1 = l1; }
            }

            const int vbase = tig * 264 + ks * 2112;
            #pragma unroll
            for (int jn = 0; jn < 16; jn++) {
                int a = vbase + (jn * 8 + gid) * 2;
                uint2 u2a = *(const uint2*)(VIb + a);          // (bh0, bl0)
                uint2 u2b = *(const uint2*)(VIb + a + 1056);   // (bh1, bl1)
                mma16816(acc[jn][0], acc[jn][1], acc[jn][2], acc[jn][3],
                         HA0, HA1, HB0, HB1, u2a.x, u2b.x);
                mma16816(acc[jn][0], acc[jn][1], acc[jn][2], acc[jn][3],
                         HA0, HA1, HB0, HB1, u2a.y, u2b.y);
                mma16816(acc[jn][0], acc[jn][1], acc[jn][2], acc[jn][3],
                         LA0, LA1, LB0, LB1, u2a.x, u2b.x);
            }
        }
        __syncthreads();
    }

    float* o0 = out + r0g * Fd + tig * 2;
    float* o1 = out + r1g * Fd + tig * 2;
    #pragma unroll
    for (int jn = 0; jn < 16; jn++) {
        *(float2*)(o0 + jn * 8) = make_float2(acc[jn][0], acc[jn][1]);
        *(float2*)(o1 + jn * 8) = make_float2(acc[jn][2], acc[jn][3]);
    }
}

extern "C" void kernel_launch(void* const* d_in, const int* in_sizes, int n_in,
                              void* d_out, int out_size) {
    const float* q   = (const float*)d_in[0];
    const float* k   = (const float*)d_in[1];
    const float* v   = (const float*)d_in[2];
    const float* cq  = (const float*)d_in[3];
    const float* ck  = (const float*)d_in[4];
    const int* am    = (const int*)d_in[5];
    const int* alm   = (const int*)d_in[6];
    const float* bs  = (const float*)d_in[7];
    const float* rm  = (const float*)d_in[8];
    float* out = (float*)d_out;

    cudaFuncSetAttribute(lsum_kernel,
                         cudaFuncAttributeMaxDynamicSharedMemorySize, SMEM1_BYTES);
    cudaFuncSetAttribute(alibi_main_kernel,
                         cudaFuncAttributeMaxDynamicSharedMemorySize, SMEM_BYTES);

    dim3 grid(Qd / 128, Bb);
    lsum_kernel<<<grid, NT, SMEM1_BYTES>>>(q, k);
    alibi_main_kernel<<<grid, NT, SMEM_BYTES>>>(q, k, v, cq, ck, am, alm, bs, rm, out);
}

// round 11
// speedup vs baseline: 1.1821x; 1.1821x over previous
#include <cuda_runtime.h>
#include <cuda_bf16.h>
#include <stdint.h>

#define Bb 16
#define Qd 2048
#define Kd 2048
#define Fd 128
#define QT 64
#define KT 64
#define NT 128

// smem word offsets (uint32 words)
#define W_QS   0                      // [64][68]
#define W_KS   (64*68)                // [64][68]
#define W_VI   (2*64*68)              // interleaved V: [32 kw][264]
#define SMEM_WORDS (W_VI + 32*264)
#define SMEM_BYTES (SMEM_WORDS*4)
#define SMEM1_BYTES (2*64*68*4)

#define PACKBF2(r, lo, hi) asm("cvt.rn.bf16x2.f32 %0, %1, %2;" : "=r"(r) : "f"(hi), "f"(lo))
#define EX2(d, x) asm("ex2.approx.f32 %0, %1;" : "=f"(d) : "f"(x))
#define SQRTA(d, x) asm("sqrt.approx.f32 %0, %1;" : "=f"(d) : "f"(x))

__device__ float g_lsum[Bb * Qd];

__device__ __forceinline__ void mma16816(float& c0, float& c1, float& c2, float& c3,
                                         uint32_t a0, uint32_t a1, uint32_t a2, uint32_t a3,
                                         uint32_t b0, uint32_t b1) {
    asm volatile("mma.sync.aligned.m16n8k16.row.col.f32.bf16.bf16.f32 "
        "{%0,%1,%2,%3}, {%4,%5,%6,%7}, {%8,%9}, {%0,%1,%2,%3};"
        : "+f"(c0), "+f"(c1), "+f"(c2), "+f"(c3)
        : "r"(a0), "r"(a1), "r"(a2), "r"(a3), "r"(b0), "r"(b1));
}

#define LDSM4(d0, d1, d2, d3, addr) \
    asm volatile("ldmatrix.sync.aligned.m8n8.x4.shared.b16 {%0,%1,%2,%3}, [%4];" \
        : "=r"(d0), "=r"(d1), "=r"(d2), "=r"(d3) : "r"(addr))

extern __shared__ uint32_t smw[];

// ---------------- kernel 1: softmax denominators ----------------
__global__ void __launch_bounds__(NT, 2) lsum_kernel(
    const float* __restrict__ q, const float* __restrict__ k)
{
    const int b = blockIdx.y, q0 = blockIdx.x * QT;
    const int tid = threadIdx.x;
    const int wid = tid >> 5, lane = tid & 31;
    const int gid = lane >> 2, tig = lane & 3;

    uint32_t* QS = smw;
    uint32_t* KS = smw + 64*68;

    const float C1 = 0.12753859788f;   // log2(e)/sqrt(128)
    const float C0 = -23.0831206f;     // -16*log2(e)

    {
        const float* qp = q + ((size_t)b * Qd + q0) * Fd;
        #pragma unroll
        for (int it = 0; it < 16; it++) {
            int widx = tid + it * NT;           // 2048 float4 = 64 rows x 32
            int row = widx >> 5, w4 = widx & 31;
            float4 t = *(const float4*)(qp + row * Fd + 4 * w4);
            uint32_t p0, p1;
            PACKBF2(p0, t.x, t.y);
            PACKBF2(p1, t.z, t.w);
            *(uint2*)(QS + row * 68 + 2 * w4) = make_uint2(p0, p1);
        }
    }

    const int lm = lane >> 3, lr = lane & 7;
    const uint32_t qsb = (uint32_t)__cvta_generic_to_shared(QS);
    const uint32_t ksb = (uint32_t)__cvta_generic_to_shared(KS);
    const uint32_t aAddr0 = qsb + (((wid * 16 + ((lm & 1) << 3) + lr) * 68) + ((lm >> 1) << 2)) * 4;
    const uint32_t bAddr0 = ksb + (((((lm >> 1) << 3) + lr) * 68) + ((lm & 1) << 2)) * 4;

    float lsum0 = 0.f, lsum1 = 0.f;

    for (int t = 0; t < 32; t++) {
        const int k0 = t * KT;
        {
            const float* kp = k + ((size_t)b * Kd + k0) * Fd;
            #pragma unroll
            for (int it = 0; it < 16; it++) {
                int widx = tid + it * NT;
                int row = widx >> 5, w4 = widx & 31;
                float4 tt = *(const float4*)(kp + row * Fd + 4 * w4);
                uint32_t p0, p1;
                PACKBF2(p0, tt.x, tt.y);
                PACKBF2(p1, tt.z, tt.w);
                *(uint2*)(KS + row * 68 + 2 * w4) = make_uint2(p0, p1);
            }
        }
        __syncthreads();

        float sc[8][4];
        #pragma unroll
        for (int j = 0; j < 8; j++)
            #pragma unroll
            for (int c = 0; c < 4; c++) sc[j][c] = 0.f;

        #pragma unroll
        for (int ks = 0; ks < 8; ks++) {
            uint32_t a0, a1, a2, a3;
            LDSM4(a0, a1, a2, a3, aAddr0 + ks * 32);
            #pragma unroll
            for (int jp = 0; jp < 4; jp++) {
                uint32_t b0, b1, b2, b3;
                LDSM4(b0, b1, b2, b3, bAddr0 + jp * (16 * 68 * 4) + ks * 32);
                mma16816(sc[2*jp][0], sc[2*jp][1], sc[2*jp][2], sc[2*jp][3],
                         a0, a1, a2, a3, b0, b1);
                mma16816(sc[2*jp+1][0], sc[2*jp+1][1], sc[2*jp+1][2], sc[2*jp+1][3],
                         a0, a1, a2, a3, b2, b3);
            }
        }
        #pragma unroll
        for (int j = 0; j < 8; j++) {
            float e0, e1, e2, e3;
            EX2(e0, fmaf(sc[j][0], C1, C0));
            EX2(e1, fmaf(sc[j][1], C1, C0));
            EX2(e2, fmaf(sc[j][2], C1, C0));
            EX2(e3, fmaf(sc[j][3], C1, C0));
            lsum0 += e0 + e1;
            lsum1 += e2 + e3;
        }
        __syncthreads();
    }

    lsum0 += __shfl_xor_sync(0xffffffffu, lsum0, 1);
    lsum0 += __shfl_xor_sync(0xffffffffu, lsum0, 2);
    lsum1 += __shfl_xor_sync(0xffffffffu, lsum1, 1);
    lsum1 += __shfl_xor_sync(0xffffffffu, lsum1, 2);
    if (tig == 0) {
        g_lsum[(size_t)b * Qd + q0 + wid * 16 + gid] = lsum0;
        g_lsum[(size_t)b * Qd + q0 + wid * 16 + gid + 8] = lsum1;
    }
}

// ---------------- kernel 2: P = softmax - dist, O = P @ V ----------------
__global__ void __launch_bounds__(NT, 2) alibi_main_kernel(
    const float* __restrict__ q, const float* __restrict__ k, const float* __restrict__ v,
    const float* __restrict__ cq, const float* __restrict__ ck,
    const int* __restrict__ am, const int* __restrict__ alm,
    const float* __restrict__ bias_scale, const float* __restrict__ running_mean,
    float* __restrict__ out)
{
    const int b = blockIdx.y, q0 = blockIdx.x * QT;
    const int tid = threadIdx.x;
    const int wid = tid >> 5, lane = tid & 31;
    const int gid = lane >> 2, tig = lane & 3;

    uint32_t* QS = smw + W_QS;
    uint32_t* KS = smw + W_KS;
    uint32_t* VI = smw + W_VI;

    const float dscale = bias_scale[0] / running_mean[0];
    const float C1 = 0.12753859788f;
    const float C0 = -23.0831206f;

    {
        const float* qp = q + ((size_t)b * Qd + q0) * Fd;
        #pragma unroll
        for (int it = 0; it < 16; it++) {
            int widx = tid + it * NT;
            int row = widx >> 5, w4 = widx & 31;
            float4 t = *(const float4*)(qp + row * Fd + 4 * w4);
            uint32_t p0, p1;
            PACKBF2(p0, t.x, t.y);
            PACKBF2(p1, t.z, t.w);
            *(uint2*)(QS + row * 68 + 2 * w4) = make_uint2(p0, p1);
        }
    }

    const int r0l = wid * 16 + gid;
    const size_t r0g = (size_t)b * Qd + q0 + r0l;
    const size_t r1g = r0g + 8;
    const float cqx0 = cq[2 * r0g], cqy0 = cq[2 * r0g + 1];
    const float cqx1 = cq[2 * r1g], cqy1 = cq[2 * r1g + 1];
    const size_t m0 = r0g * (size_t)Kd, m1 = r1g * (size_t)Kd;
    const float inv0 = 1.f / g_lsum[r0g];
    const float inv1 = 1.f / g_lsum[r1g];

    const int lm = lane >> 3, lr = lane & 7;
    const uint32_t qsb = (uint32_t)__cvta_generic_to_shared(QS);
    const uint32_t ksb = (uint32_t)__cvta_generic_to_shared(KS);
    const uint32_t aAddr0 = qsb + (((wid * 16 + ((lm & 1) << 3) + lr) * 68) + ((lm >> 1) << 2)) * 4;
    const uint32_t bAddr0 = ksb + (((((lm >> 1) << 3) + lr) * 68) + ((lm & 1) << 2)) * 4;

    float acc[16][4];
    #pragma unroll
    for (int jn = 0; jn < 16; jn++)
        #pragma unroll
        for (int c = 0; c < 4; c++) acc[jn][c] = 0.f;

    for (int t = 0; t < 32; t++) {
        const int k0 = t * KT;

        {
            const float* kp = k + ((size_t)b * Kd + k0) * Fd;
            #pragma unroll
            for (int it = 0; it < 16; it++) {
                int widx = tid + it * NT;
                int row = widx >> 5, w4 = widx & 31;
                float4 tt = *(const float4*)(kp + row * Fd + 4 * w4);
                uint32_t p0, p1;
                PACKBF2(p0, tt.x, tt.y);
                PACKBF2(p1, tt.z, tt.w);
                *(uint2*)(KS + row * 68 + 2 * w4) = make_uint2(p0, p1);
            }
        }
        {
            // V interleaved hi/lo: VI[kw*264 + f*2 + {0:hi,1:lo}]
            const float* vp = v + ((size_t)b * Kd + k0) * Fd;
            #pragma unroll
            for (int it = 0; it < 8; it++) {
                int idx = tid + it * NT;           // 1024 = 32 kw x 32 fq
                int fq = idx & 31, kw = idx >> 5;
                const float* va = vp + (size_t)(2 * kw) * Fd + 4 * fq;
                float4 a = *(const float4*)va;
                float4 bb = *(const float4*)(va + Fd);
                uint32_t ph0, ph1, ph2, ph3;
                PACKBF2(ph0, a.x, bb.x);
                PACKBF2(ph1, a.y, bb.y);
                PACKBF2(ph2, a.z, bb.z);
                PACKBF2(ph3, a.w, bb.w);
                uint32_t pl0, pl1, pl2, pl3;
                float r0, r1;
                r0 = a.x - __uint_as_float(ph0 << 16); r1 = bb.x - __uint_as_float(ph0 & 0xffff0000u);
                PACKBF2(pl0, r0, r1);
                r0 = a.y - __uint_as_float(ph1 << 16); r1 = bb.y - __uint_as_float(ph1 & 0xffff0000u);
                PACKBF2(pl1, r0, r1);
                r0 = a.z - __uint_as_float(ph2 << 16); r1 = bb.z - __uint_as_float(ph2 & 0xffff0000u);
                PACKBF2(pl2, r0, r1);
                r0 = a.w - __uint_as_float(ph3 << 16); r1 = bb.w - __uint_as_float(ph3 & 0xffff0000u);
                PACKBF2(pl3, r0, r1);
                int base = kw * 264 + 8 * fq;
                *(uint4*)(VI + base)     = make_uint4(ph0, pl0, ph1, pl1);
                *(uint4*)(VI + base + 4) = make_uint4(ph2, pl2, ph3, pl3);
            }
        }
        __syncthreads();

        // ---- S = Q @ K^T via ldmatrix ----
        float sc[8][4];
        #pragma unroll
        for (int j = 0; j < 8; j++)
            #pragma unroll
            for (int c = 0; c < 4; c++) sc[j][c] = 0.f;

        #pragma unroll
        for (int ks = 0; ks < 8; ks++) {
            uint32_t a0, a1, a2, a3;
            LDSM4(a0, a1, a2, a3, aAddr0 + ks * 32);
            #pragma unroll
            for (int jp = 0; jp < 4; jp++) {
                uint32_t b0, b1, b2, b3;
                LDSM4(b0, b1, b2, b3, bAddr0 + jp * (16 * 68 * 4) + ks * 32);
                mma16816(sc[2*jp][0], sc[2*jp][1], sc[2*jp][2], sc[2*jp][3],
                         a0, a1, a2, a3, b0, b1);
                mma16816(sc[2*jp+1][0], sc[2*jp+1][1], sc[2*jp+1][2], sc[2*jp+1][3],
                         a0, a1, a2, a3, b2, b3);
            }
        }

        // ---- per k16-chunk: elementwise P, then PV ----
        #pragma unroll
        for (int ks = 0; ks < 4; ks++) {
            uint32_t HA0, HA1, HB0, HB1, LA0, LA1, LB0, LB1;
            #pragma unroll
            for (int jj = 0; jj < 2; jj++) {
                int j = 2 * ks + jj;
                int c0 = k0 + j * 8 + tig * 2;
                float4 ckv = *(const float4*)(ck + ((size_t)b * Kd + c0) * 2);
                int2 a0m = *(const int2*)(am  + m0 + c0);
                int2 a1m = *(const int2*)(am  + m1 + c0);
                int2 l0m = *(const int2*)(alm + m0 + c0);
                int2 l1m = *(const int2*)(alm + m1 + c0);

                float e00, e01, e10, e11;
                EX2(e00, fmaf(sc[j][0], C1, C0));
                EX2(e01, fmaf(sc[j][1], C1, C0));
                EX2(e10, fmaf(sc[j][2], C1, C0));
                EX2(e11, fmaf(sc[j][3], C1, C0));

                float dxa = cqx0 - ckv.x, dya = cqy0 - ckv.y;
                float dxb = cqx0 - ckv.z, dyb = cqy0 - ckv.w;
                float dxc = cqx1 - ckv.x, dyc = cqy1 - ckv.y;
                float dxd = cqx1 - ckv.z, dyd = cqy1 - ckv.w;
                float d00, d01, d10, d11;
                SQRTA(d00, fmaf(dxa, dxa, dya * dya));
                SQRTA(d01, fmaf(dxb, dxb, dyb * dyb));
                SQRTA(d10, fmaf(dxc, dxc, dyc * dyc));
                SQRTA(d11, fmaf(dxd, dxd, dyd * dyd));

                d00 = (a0m.x | l0m.x) ? 0.f : d00 * dscale;
                d01 = (a0m.y | l0m.y) ? 0.f : d01 * dscale;
                d10 = (a1m.x | l1m.x) ? 0.f : d10 * dscale;
                d11 = (a1m.y | l1m.y) ? 0.f : d11 * dscale;

                float p00 = (a0m.x ? 0.f : e00 * inv0) - d00;
                float p01 = (a0m.y ? 0.f : e01 * inv0) - d01;
                float p10 = (a1m.x ? 0.f : e10 * inv1) - d10;
                float p11 = (a1m.y ? 0.f : e11 * inv1) - d11;

                uint32_t h0, h1, l0, l1;
                PACKBF2(h0, p00, p01);
                PACKBF2(h1, p10, p11);
                float q00 = p00 - __uint_as_float(h0 << 16);
                float q01 = p01 - __uint_as_float(h0 & 0xffff0000u);
                float q10 = p10 - __uint_as_float(h1 << 16);
                float q11 = p11 - __uint_as_float(h1 & 0xffff0000u);
                PACKBF2(l0, q00, q01);
                PACKBF2(l1, q10, q11);
                if (jj == 0) { HA0 = h0; HA1 = h1; LA0 = l0; LA1 = l1; }
                else         { HB0 = h0; HB1 = h1; LB0 = l0; LB1 = l1; }
            }

            const int vbase = tig * 264 + ks * 2112;
            #pragma unroll
            for (int jn = 0; jn < 16; jn++) {
                int a = vbase + (jn * 8 + gid) * 2;
                uint2 u2a = *(const uint2*)(VI + a);          // (bh0, bl0)
                uint2 u2b = *(const uint2*)(VI + a + 1056);   // (bh1, bl1)
                mma16816(acc[jn][0], acc[jn][1], acc[jn][2], acc[jn][3],
                         HA0, HA1, HB0, HB1, u2a.x, u2b.x);
                mma16816(acc[jn][0], acc[jn][1], acc[jn][2], acc[jn][3],
                         HA0, HA1, HB0, HB1, u2a.y, u2b.y);
                mma16816(acc[jn][0], acc[jn][1], acc[jn][2], acc[jn][3],
                         LA0, LA1, LB0, LB1, u2a.x, u2b.x);
            }
        }
        __syncthreads();
    }

    float* o0 = out + r0g * Fd + tig * 2;
    float* o1 = out + r1g * Fd + tig * 2;
    #pragma unroll
    for (int jn = 0; jn < 16; jn++) {
        *(float2*)(o0 + jn * 8) = make_float2(acc[jn][0], acc[jn][1]);
        *(float2*)(o1 + jn * 8) = make_float2(acc[jn][2], acc[jn][3]);
    }
}

extern "C" void kernel_launch(void* const* d_in, const int* in_sizes, int n_in,
                              void* d_out, int out_size) {
    const float* q   = (const float*)d_in[0];
    const float* k   = (const float*)d_in[1];
    const float* v   = (const float*)d_in[2];
    const float* cq  = (const float*)d_in[3];
    const float* ck  = (const float*)d_in[4];
    const int* am    = (const int*)d_in[5];
    const int* alm   = (const int*)d_in[6];
    const float* bs  = (const float*)d_in[7];
    const float* rm  = (const float*)d_in[8];
    float* out = (float*)d_out;

    cudaFuncSetAttribute(lsum_kernel,
                         cudaFuncAttributeMaxDynamicSharedMemorySize, SMEM1_BYTES);
    cudaFuncSetAttribute(alibi_main_kernel,
                         cudaFuncAttributeMaxDynamicSharedMemorySize, SMEM_BYTES);

    dim3 grid(Qd / QT, Bb);
    lsum_kernel<<<grid, NT, SMEM1_BYTES>>>(q, k);
    alibi_main_kernel<<<grid, NT, SMEM_BYTES>>>(q, k, v, cq, ck, am, alm, bs, rm, out);
}

// round 12
// speedup vs baseline: 1.5101x; 1.2774x over previous
#include <cuda_runtime.h>
#include <cuda_bf16.h>
#include <cuda_fp16.h>
#include <stdint.h>

#define Bb 16
#define Qd 2048
#define Kd 2048
#define Fd 128
#define KT 64
#define NT 256

// ---- kernel1 smem (words): QS[128][68] + KS[64][68]
#define SMEM1_BYTES ((128*68 + 64*68)*4)
// ---- kernel2 smem: VI interleaved hi/lo [32 kw][264]
#define SMEM2_BYTES (32*264*4)

#define PACKBF2(r, lo, hi) asm("cvt.rn.bf16x2.f32 %0, %1, %2;" : "=r"(r) : "f"(hi), "f"(lo))
#define EX2(d, x) asm("ex2.approx.f32 %0, %1;" : "=f"(d) : "f"(x))
#define SQRTA(d, x) asm("sqrt.approx.f32 %0, %1;" : "=f"(d) : "f"(x))

__device__ float  g_lsum[Bb * Qd];
__device__ __half g_E[(size_t)256 * 32 * 8192];   // [cta][tile][warp*1024 + j*128 + lane*4]

__device__ __forceinline__ void mma16816(float& c0, float& c1, float& c2, float& c3,
                                         uint32_t a0, uint32_t a1, uint32_t a2, uint32_t a3,
                                         uint32_t b0, uint32_t b1) {
    asm volatile("mma.sync.aligned.m16n8k16.row.col.f32.bf16.bf16.f32 "
        "{%0,%1,%2,%3}, {%4,%5,%6,%7}, {%8,%9}, {%0,%1,%2,%3};"
        : "+f"(c0), "+f"(c1), "+f"(c2), "+f"(c3)
        : "r"(a0), "r"(a1), "r"(a2), "r"(a3), "r"(b0), "r"(b1));
}

#define LDSM4(d0, d1, d2, d3, addr) \
    asm volatile("ldmatrix.sync.aligned.m8n8.x4.shared.b16 {%0,%1,%2,%3}, [%4];" \
        : "=r"(d0), "=r"(d1), "=r"(d2), "=r"(d3) : "r"(addr))

extern __shared__ uint32_t smw[];

// ---------------- kernel 1: S = QK^T, E = exp(s/sqrt(128) - 2) -> g_E, row sums -> g_lsum ----------------
__global__ void __launch_bounds__(NT, 1) lsum_kernel(
    const float* __restrict__ q, const float* __restrict__ k)
{
    const int b = blockIdx.y, q0 = blockIdx.x * 128;
    const int cid = b * 16 + blockIdx.x;
    const int tid = threadIdx.x;
    const int wid = tid >> 5, lane = tid & 31;
    const int gid = lane >> 2, tig = lane & 3;

    uint32_t* QS = smw;
    uint32_t* KS = smw + 128 * 68;

    const float C1 = 0.12753859788f;    // log2(e)/sqrt(128)
    const float C0 = -2.88539008178f;   // -2*log2(e)

    {
        const float* qp = q + ((size_t)b * Qd + q0) * Fd;
        #pragma unroll
        for (int it = 0; it < 16; it++) {
            int widx = tid + it * 256;          // 4096 float4 = 128 rows x 32
            int row = widx >> 5, w4 = widx & 31;
            float4 t = *(const float4*)(qp + row * Fd + 4 * w4);
            uint32_t p0, p1;
            PACKBF2(p0, t.x, t.y);
            PACKBF2(p1, t.z, t.w);
            *(uint2*)(QS + row * 68 + 2 * w4) = make_uint2(p0, p1);
        }
    }

    const int lm = lane >> 3, lr = lane & 7;
    const uint32_t qsb = (uint32_t)__cvta_generic_to_shared(QS);
    const uint32_t ksb = (uint32_t)__cvta_generic_to_shared(KS);
    const uint32_t aAddr0 = qsb + (((wid * 16 + ((lm & 1) << 3) + lr) * 68) + ((lm >> 1) << 2)) * 4;
    const uint32_t bAddr0 = ksb + (((((lm >> 1) << 3) + lr) * 68) + ((lm & 1) << 2)) * 4;

    float lsum0 = 0.f, lsum1 = 0.f;

    for (int t = 0; t < 32; t++) {
        const int k0 = t * KT;
        {
            const float* kp = k + ((size_t)b * Kd + k0) * Fd;
            #pragma unroll
            for (int it = 0; it < 8; it++) {
                int widx = tid + it * 256;      // 2048 float4 = 64 rows x 32
                int row = widx >> 5, w4 = widx & 31;
                float4 tt = *(const float4*)(kp + row * Fd + 4 * w4);
                uint32_t p0, p1;
                PACKBF2(p0, tt.x, tt.y);
                PACKBF2(p1, tt.z, tt.w);
                *(uint2*)(KS + row * 68 + 2 * w4) = make_uint2(p0, p1);
            }
        }
        __syncthreads();

        float sc[8][4];
        #pragma unroll
        for (int j = 0; j < 8; j++)
            #pragma unroll
            for (int c = 0; c < 4; c++) sc[j][c] = 0.f;

        #pragma unroll
        for (int ks = 0; ks < 8; ks++) {
            uint32_t a0, a1, a2, a3;
            LDSM4(a0, a1, a2, a3, aAddr0 + ks * 32);
            #pragma unroll
            for (int jp = 0; jp < 4; jp++) {
                uint32_t b0, b1, b2, b3;
                LDSM4(b0, b1, b2, b3, bAddr0 + jp * (16 * 68 * 4) + ks * 32);
                mma16816(sc[2*jp][0], sc[2*jp][1], sc[2*jp][2], sc[2*jp][3],
                         a0, a1, a2, a3, b0, b1);
                mma16816(sc[2*jp+1][0], sc[2*jp+1][1], sc[2*jp+1][2], sc[2*jp+1][3],
                         a0, a1, a2, a3, b2, b3);
            }
        }

        const size_t eb = (((size_t)cid * 32 + t) * 8 + wid) * 1024 + lane * 4;
        #pragma unroll
        for (int j = 0; j < 8; j++) {
            float e0, e1, e2, e3;
            EX2(e0, fmaf(sc[j][0], C1, C0));
            EX2(e1, fmaf(sc[j][1], C1, C0));
            EX2(e2, fmaf(sc[j][2], C1, C0));
            EX2(e3, fmaf(sc[j][3], C1, C0));
            lsum0 += e0 + e1;
            lsum1 += e2 + e3;
            __half2 hA = __floats2half2_rn(e0, e1);
            __half2 hB = __floats2half2_rn(e2, e3);
            uint2 u;
            u.x = *(uint32_t*)&hA;
            u.y = *(uint32_t*)&hB;
            *(uint2*)&g_E[eb + j * 128] = u;
        }
        __syncthreads();
    }

    lsum0 += __shfl_xor_sync(0xffffffffu, lsum0, 1);
    lsum0 += __shfl_xor_sync(0xffffffffu, lsum0, 2);
    lsum1 += __shfl_xor_sync(0xffffffffu, lsum1, 1);
    lsum1 += __shfl_xor_sync(0xffffffffu, lsum1, 2);
    if (tig == 0) {
        g_lsum[(size_t)b * Qd + q0 + wid * 16 + gid] = lsum0;
        g_lsum[(size_t)b * Qd + q0 + wid * 16 + gid + 8] = lsum1;
    }
}

// ---------------- kernel 2: P = E*inv - dist (masked), O = P @ V  (PV-only) ----------------
__global__ void __launch_bounds__(NT, 2) alibi_main_kernel(
    const float* __restrict__ v,
    const float* __restrict__ cq, const float* __restrict__ ck,
    const int* __restrict__ am, const int* __restrict__ alm,
    const float* __restrict__ bias_scale, const float* __restrict__ running_mean,
    float* __restrict__ out)
{
    const int b = blockIdx.y, q0 = blockIdx.x * 128;
    const int cid = b * 16 + blockIdx.x;
    const int tid = threadIdx.x;
    const int wid = tid >> 5, lane = tid & 31;
    const int gid = lane >> 2, tig = lane & 3;

    uint32_t* VI = smw;

    const float dscale = bias_scale[0] / running_mean[0];

    const int r0l = wid * 16 + gid;
    const size_t r0g = (size_t)b * Qd + q0 + r0l;
    const size_t r1g = r0g + 8;
    const float cqx0 = cq[2 * r0g], cqy0 = cq[2 * r0g + 1];
    const float cqx1 = cq[2 * r1g], cqy1 = cq[2 * r1g + 1];
    const size_t m0 = r0g * (size_t)Kd, m1 = r1g * (size_t)Kd;
    const float inv0 = 1.f / g_lsum[r0g];
    const float inv1 = 1.f / g_lsum[r1g];

    float acc[16][4];
    #pragma unroll
    for (int jn = 0; jn < 16; jn++)
        #pragma unroll
        for (int c = 0; c < 4; c++) acc[jn][c] = 0.f;

    for (int t = 0; t < 32; t++) {
        const int k0 = t * KT;

        // E fragments for this tile (issued early; no smem dependency)
        uint2 Eu[8];
        {
            const size_t eb = (((size_t)cid * 32 + t) * 8 + wid) * 1024 + lane * 4;
            #pragma unroll
            for (int j = 0; j < 8; j++)
                Eu[j] = *(const uint2*)&g_E[eb + j * 128];
        }

        // V interleaved hi/lo: VI[kw*264 + f*2 + {0:hi,1:lo}]
        {
            const float* vp = v + ((size_t)b * Kd + k0) * Fd;
            #pragma unroll
            for (int it = 0; it < 4; it++) {
                int idx = tid + it * 256;            // 1024 = 32 kw x 32 fq
                int fq = idx & 31, kw = idx >> 5;
                const float* va = vp + (size_t)(2 * kw) * Fd + 4 * fq;
                float4 a = *(const float4*)va;
                float4 bb = *(const float4*)(va + Fd);
                uint32_t ph0, ph1, ph2, ph3;
                PACKBF2(ph0, a.x, bb.x);
                PACKBF2(ph1, a.y, bb.y);
                PACKBF2(ph2, a.z, bb.z);
                PACKBF2(ph3, a.w, bb.w);
                uint32_t pl0, pl1, pl2, pl3;
                float r0, r1;
                r0 = a.x - __uint_as_float(ph0 << 16); r1 = bb.x - __uint_as_float(ph0 & 0xffff0000u);
                PACKBF2(pl0, r0, r1);
                r0 = a.y - __uint_as_float(ph1 << 16); r1 = bb.y - __uint_as_float(ph1 & 0xffff0000u);
                PACKBF2(pl1, r0, r1);
                r0 = a.z - __uint_as_float(ph2 << 16); r1 = bb.z - __uint_as_float(ph2 & 0xffff0000u);
                PACKBF2(pl2, r0, r1);
                r0 = a.w - __uint_as_float(ph3 << 16); r1 = bb.w - __uint_as_float(ph3 & 0xffff0000u);
                PACKBF2(pl3, r0, r1);
                int base = kw * 264 + 8 * fq;
                *(uint4*)(VI + base)     = make_uint4(ph0, pl0, ph1, pl1);
                *(uint4*)(VI + base + 4) = make_uint4(ph2, pl2, ph3, pl3);
            }
        }
        __syncthreads();

        // ---- per k16-chunk: elementwise P, then PV ----
        #pragma unroll
        for (int ks = 0; ks < 4; ks++) {
            uint32_t HA0, HA1, HB0, HB1, LA0, LA1, LB0, LB1;
            #pragma unroll
            for (int jj = 0; jj < 2; jj++) {
                int j = 2 * ks + jj;
                int c0 = k0 + j * 8 + tig * 2;
                float4 ckv = *(const float4*)(ck + ((size_t)b * Kd + c0) * 2);
                int2 a0m = *(const int2*)(am  + m0 + c0);
                int2 a1m = *(const int2*)(am  + m1 + c0);
                int2 l0m = *(const int2*)(alm + m0 + c0);
                int2 l1m = *(const int2*)(alm + m1 + c0);

                float2 fA = __half22float2(*(__half2*)&Eu[j].x);
                float2 fB = __half22float2(*(__half2*)&Eu[j].y);
                float e00 = fA.x, e01 = fA.y, e10 = fB.x, e11 = fB.y;

                float dxa = cqx0 - ckv.x, dya = cqy0 - ckv.y;
                float dxb = cqx0 - ckv.z, dyb = cqy0 - ckv.w;
                float dxc = cqx1 - ckv.x, dyc = cqy1 - ckv.y;
                float dxd = cqx1 - ckv.z, dyd = cqy1 - ckv.w;
                float d00, d01, d10, d11;
                SQRTA(d00, fmaf(dxa, dxa, dya * dya));
                SQRTA(d01, fmaf(dxb, dxb, dyb * dyb));
                SQRTA(d10, fmaf(dxc, dxc, dyc * dyc));
                SQRTA(d11, fmaf(dxd, dxd, dyd * dyd));

                d00 = (a0m.x | l0m.x) ? 0.f : d00 * dscale;
                d01 = (a0m.y | l0m.y) ? 0.f : d01 * dscale;
                d10 = (a1m.x | l1m.x) ? 0.f : d10 * dscale;
                d11 = (a1m.y | l1m.y) ? 0.f : d11 * dscale;

                float p00 = (a0m.x ? 0.f : e00 * inv0) - d00;
                float p01 = (a0m.y ? 0.f : e01 * inv0) - d01;
                float p10 = (a1m.x ? 0.f : e10 * inv1) - d10;
                float p11 = (a1m.y ? 0.f : e11 * inv1) - d11;

                uint32_t h0, h1, l0, l1;
                PACKBF2(h0, p00, p01);
                PACKBF2(h1, p10, p11);
                float q00 = p00 - __uint_as_float(h0 << 16);
                float q01 = p01 - __uint_as_float(h0 & 0xffff0000u);
                float q10 = p10 - __uint_as_float(h1 << 16);
                float q11 = p11 - __uint_as_float(h1 & 0xffff0000u);
                PACKBF2(l0, q00, q01);
                PACKBF2(l1, q10, q11);
                if (jj == 0) { HA0 = h0; HA1 = h1; LA0 = l0; LA1 = l1; }
                else         { HB0 = h0; HB1 = h1; LB0 = l0; LB1 = l1; }
            }

            const int vbase = tig * 264 + ks * 2112;
            #pragma unroll
            for (int jn = 0; jn < 16; jn++) {
                int a = vbase + (jn * 8 + gid) * 2;
                uint2 u2a = *(const uint2*)(VI + a);          // (bh0, bl0)
                uint2 u2b = *(const uint2*)(VI + a + 1056);   // (bh1, bl1)
                mma16816(acc[jn][0], acc[jn][1], acc[jn][2], acc[jn][3],
                         HA0, HA1, HB0, HB1, u2a.x, u2b.x);
                mma16816(acc[jn][0], acc[jn][1], acc[jn][2], acc[jn][3],
                         HA0, HA1, HB0, HB1, u2a.y, u2b.y);
                mma16816(acc[jn][0], acc[jn][1], acc[jn][2], acc[jn][3],
                         LA0, LA1, LB0, LB1, u2a.x, u2b.x);
            }
        }
        __syncthreads();
    }

    float* o0 = out + r0g * Fd + tig * 2;
    float* o1 = out + r1g * Fd + tig * 2;
    #pragma unroll
    for (int jn = 0; jn < 16; jn++) {
        *(float2*)(o0 + jn * 8) = make_float2(acc[jn][0], acc[jn][1]);
        *(float2*)(o1 + jn * 8) = make_float2(acc[jn][2], acc[jn][3]);
    }
}

extern "C" void kernel_launch(void* const* d_in, const int* in_sizes, int n_in,
                              void* d_out, int out_size) {
    const float* q   = (const float*)d_in[0];
    const float* k   = (const float*)d_in[1];
    const float* v   = (const float*)d_in[2];
    const float* cq  = (const float*)d_in[3];
    const float* ck  = (const float*)d_in[4];
    const int* am    = (const int*)d_in[5];
    const int* alm   = (const int*)d_in[6];
    const float* bs  = (const float*)d_in[7];
    const float* rm  = (const float*)d_in[8];
    float* out = (float*)d_out;

    cudaFuncSetAttribute(lsum_kernel,
                         cudaFuncAttributeMaxDynamicSharedMemorySize, SMEM1_BYTES);
    cudaFuncSetAttribute(alibi_main_kernel,
                         cudaFuncAttributeMaxDynamicSharedMemorySize, SMEM2_BYTES);

    dim3 grid(Qd / 128, Bb);
    lsum_kernel<<<grid, NT, SMEM1_BYTES>>>(q, k);
    alibi_main_kernel<<<grid, NT, SMEM2_BYTES>>>(v, cq, ck, am, alm, bs, rm, out);
}